// round 3
// baseline (speedup 1.0000x reference)
#include <cuda_runtime.h>
#include <cstdint>

// Problem constants (fixed by the dataset)
#define NE     1600000
#define D      128
#define TWO_D  256
#define SEG    50000

#define NEG_INF __int_as_float(0xFF800000)

// Scratch: device globals (no cudaMalloc allowed)
static __device__ int g_cnt[SEG];        // histogram
static __device__ int g_offs[SEG + 1];   // exclusive offsets
static __device__ int g_cur[SEG];        // rank cursors
static __device__ int g_perm[NE];        // edge ids grouped by segment

// ---------------------------------------------------------------------------
// Kernel 1: zero histogram
// ---------------------------------------------------------------------------
__global__ void __launch_bounds__(256) zero_cnt_kernel() {
    int i = blockIdx.x * 256 + threadIdx.x;
    if (i < SEG) g_cnt[i] = 0;
}

// ---------------------------------------------------------------------------
// Kernel 2: histogram of index (int4 loads, fire-and-forget adds)
// ---------------------------------------------------------------------------
__global__ void __launch_bounds__(256) hist_kernel(const int* __restrict__ index) {
    int i = blockIdx.x * 256 + threadIdx.x;
    if (i < NE / 4) {
        int4 s = ((const int4*)index)[i];
        atomicAdd(&g_cnt[s.x], 1);
        atomicAdd(&g_cnt[s.y], 1);
        atomicAdd(&g_cnt[s.z], 1);
        atomicAdd(&g_cnt[s.w], 1);
    }
}

// ---------------------------------------------------------------------------
// Kernel 3: exclusive scan of 50K counters. One block, 1024 threads.
// ---------------------------------------------------------------------------
__global__ void __launch_bounds__(1024) scan_kernel() {
    __shared__ int part[1024];
    const int CH = 49;                     // 1024*49 = 50176 >= 50000
    int t  = threadIdx.x;
    int lo = t * CH;
    int hi = lo + CH; if (hi > SEG) hi = SEG;
    if (lo > SEG) lo = SEG;

    int s = 0;
    for (int i = lo; i < hi; i++) s += g_cnt[i];
    part[t] = s;
    __syncthreads();

    for (int off = 1; off < 1024; off <<= 1) {
        int v = 0;
        if (t >= off) v = part[t - off];
        __syncthreads();
        if (t >= off) part[t] += v;
        __syncthreads();
    }

    int run = (t == 0) ? 0 : part[t - 1];
    for (int i = lo; i < hi; i++) {
        g_offs[i] = run;
        g_cur[i]  = run;
        run += g_cnt[i];
    }
    if (t == 1023) g_offs[SEG] = part[1023];
}

// ---------------------------------------------------------------------------
// Kernel 4: build permutation, 4 edges per thread (MLP=4 on the
// load -> atomic -> store chains)
// ---------------------------------------------------------------------------
__global__ void __launch_bounds__(256) rank_kernel(const int* __restrict__ index) {
    int i = blockIdx.x * 256 + threadIdx.x;
    if (i < NE / 4) {
        int4 s = ((const int4*)index)[i];
        int e = i * 4;
        int p0 = atomicAdd(&g_cur[s.x], 1);
        int p1 = atomicAdd(&g_cur[s.y], 1);
        int p2 = atomicAdd(&g_cur[s.z], 1);
        int p3 = atomicAdd(&g_cur[s.w], 1);
        g_perm[p0] = e;
        g_perm[p1] = e + 1;
        g_perm[p2] = e + 2;
        g_perm[p3] = e + 3;
    }
}

// ---------------------------------------------------------------------------
// Kernel 5 (FUSED): segment reduce -> smem cat tile -> register-tiled GEMM.
//
// Block = 256 threads (8 warps), tile = 32 segments x 128 output cols.
// Phase 1: warp w reduces segments {row0 + 4w + j}, j=0..3. Lane owns 4
//          consecutive features; float4 streaming loads, register acc,
//          write full 256-wide cat row into As[m][256].
// Phase 2: GEMM. ty = warp -> 4 rows, tx = lane -> col pairs (2tx, 2tx+1)
//          and (64+2tx, 64+2tx+1). W staged per BK=16 chunk in Bs[k][d].
//          packed fma.rn.f32x2 accumulators.
// ---------------------------------------------------------------------------
#define BM  32
#define BKC 16
#define BSS 132   // Bs row stride (words)

__global__ void __launch_bounds__(256) fused_kernel(const float* __restrict__ src,
                                                    const float* __restrict__ W,
                                                    const float* __restrict__ bias,
                                                    float* __restrict__ out) {
    __shared__ float As[BM][TWO_D];       // 32 KB: full cat rows
    __shared__ float Bs[BKC * BSS];       // 8.25 KB: W chunk, k-major

    int tid  = threadIdx.x;
    int w    = tid >> 5;
    int lane = tid & 31;
    int row0 = blockIdx.x * BM;

    // ---------------- Phase 1: reduce 4 segments per warp ----------------
    #pragma unroll
    for (int j = 0; j < 4; j++) {
        int m   = w * 4 + j;
        int seg = row0 + m;

        float4 sum = make_float4(0.f, 0.f, 0.f, 0.f);
        float4 mx  = make_float4(NEG_INF, NEG_INF, NEG_INF, NEG_INF);

        if (seg < SEG) {
            int start = __ldg(&g_offs[seg]);
            int end   = __ldg(&g_offs[seg + 1]);

            int i = start;
            for (; i + 1 < end; i += 2) {
                int e0 = __ldg(&g_perm[i]);
                int e1 = __ldg(&g_perm[i + 1]);
                float4 v0 = __ldcs((const float4*)(src + (size_t)e0 * D) + lane);
                float4 v1 = __ldcs((const float4*)(src + (size_t)e1 * D) + lane);
                sum.x += v0.x; sum.y += v0.y; sum.z += v0.z; sum.w += v0.w;
                mx.x = fmaxf(mx.x, v0.x); mx.y = fmaxf(mx.y, v0.y);
                mx.z = fmaxf(mx.z, v0.z); mx.w = fmaxf(mx.w, v0.w);
                sum.x += v1.x; sum.y += v1.y; sum.z += v1.z; sum.w += v1.w;
                mx.x = fmaxf(mx.x, v1.x); mx.y = fmaxf(mx.y, v1.y);
                mx.z = fmaxf(mx.z, v1.z); mx.w = fmaxf(mx.w, v1.w);
            }
            if (i < end) {
                int e0 = __ldg(&g_perm[i]);
                float4 v0 = __ldcs((const float4*)(src + (size_t)e0 * D) + lane);
                sum.x += v0.x; sum.y += v0.y; sum.z += v0.z; sum.w += v0.w;
                mx.x = fmaxf(mx.x, v0.x); mx.y = fmaxf(mx.y, v0.y);
                mx.z = fmaxf(mx.z, v0.z); mx.w = fmaxf(mx.w, v0.w);
            }
            if (start == end)             // torch_scatter: empty max = 0
                mx = make_float4(0.f, 0.f, 0.f, 0.f);
        } else {
            mx = make_float4(0.f, 0.f, 0.f, 0.f);
        }

        *(float4*)&As[m][lane * 4]       = sum;
        *(float4*)&As[m][D + lane * 4]   = mx;
    }
    __syncthreads();

    // ---------------- Phase 2: GEMM out = cat @ W^T + b ----------------
    int tx = lane;      // col pairs (2tx, 2tx+1) and (64+2tx, 64+2tx+1)
    int ty = w;         // rows ty*4 .. ty*4+3

    unsigned long long acc2[4][2];
    #pragma unroll
    for (int i = 0; i < 4; i++) { acc2[i][0] = 0ull; acc2[i][1] = 0ull; }

    for (int kc = 0; kc < TWO_D; kc += BKC) {
        // stage Bs[k][d] = W[d][kc + k], k in [0,16)
        #pragma unroll
        for (int l = 0; l < 2; l++) {
            int idx = tid + l * 256;
            int d   = idx >> 2;          // 0..127
            int k4  = (idx & 3) * 4;     // 0,4,8,12
            float4 v = *(const float4*)(W + (size_t)d * TWO_D + kc + k4);
            Bs[(k4 + 0) * BSS + d] = v.x;
            Bs[(k4 + 1) * BSS + d] = v.y;
            Bs[(k4 + 2) * BSS + d] = v.z;
            Bs[(k4 + 3) * BSS + d] = v.w;
        }
        __syncthreads();

        #pragma unroll
        for (int kk = 0; kk < BKC; kk += 4) {
            float a[4][4];
            #pragma unroll
            for (int i = 0; i < 4; i++)
                *(float4*)a[i] = *(const float4*)&As[ty * 4 + i][kc + kk];

            #pragma unroll
            for (int q = 0; q < 4; q++) {
                unsigned long long b0 = *(const unsigned long long*)(Bs + (kk + q) * BSS + 2 * tx);
                unsigned long long b1 = *(const unsigned long long*)(Bs + (kk + q) * BSS + 64 + 2 * tx);
                #pragma unroll
                for (int i = 0; i < 4; i++) {
                    unsigned long long asplat;
                    asm("mov.b64 %0, {%1, %1};" : "=l"(asplat) : "f"(a[i][q]));
                    asm("fma.rn.f32x2 %0, %1, %2, %0;" : "+l"(acc2[i][0]) : "l"(asplat), "l"(b0));
                    asm("fma.rn.f32x2 %0, %1, %2, %0;" : "+l"(acc2[i][1]) : "l"(asplat), "l"(b1));
                }
            }
        }
        __syncthreads();
    }

    float2 bb0 = *(const float2*)(bias + 2 * tx);
    float2 bb1 = *(const float2*)(bias + 64 + 2 * tx);
    #pragma unroll
    for (int i = 0; i < 4; i++) {
        int gr = row0 + ty * 4 + i;
        if (gr < SEG) {
            float x0, x1, x2, x3;
            asm("mov.b64 {%0, %1}, %2;" : "=f"(x0), "=f"(x1) : "l"(acc2[i][0]));
            asm("mov.b64 {%0, %1}, %2;" : "=f"(x2), "=f"(x3) : "l"(acc2[i][1]));
            *(float2*)(out + (size_t)gr * D + 2 * tx)      = make_float2(x0 + bb0.x, x1 + bb0.y);
            *(float2*)(out + (size_t)gr * D + 64 + 2 * tx) = make_float2(x2 + bb1.x, x3 + bb1.y);
        }
    }
}

// ---------------------------------------------------------------------------
// Launch pipeline: zero -> hist -> scan -> rank -> fused(reduce+gemm)
// Inputs (metadata order): src[f32 NE*D], index[i32 NE], W[f32 D*2D], b[f32 D]
// ---------------------------------------------------------------------------
extern "C" void kernel_launch(void* const* d_in, const int* in_sizes, int n_in,
                              void* d_out, int out_size) {
    const float* src   = (const float*)d_in[0];
    const int*   index = (const int*)d_in[1];
    const float* W     = (const float*)d_in[2];
    const float* bias  = (const float*)d_in[3];
    float* out = (float*)d_out;

    (void)in_sizes; (void)n_in; (void)out_size;

    zero_cnt_kernel<<<(SEG + 255) / 256, 256>>>();
    hist_kernel<<<(NE / 4 + 255) / 256, 256>>>(index);
    scan_kernel<<<1, 1024>>>();
    rank_kernel<<<(NE / 4 + 255) / 256, 256>>>(index);
    fused_kernel<<<(SEG + BM - 1) / BM, 256>>>(src, W, bias, out);
}

// round 4
// speedup vs baseline: 1.1159x; 1.1159x over previous
#include <cuda_runtime.h>
#include <cstdint>

// Problem constants (fixed by the dataset)
#define NE     1600000
#define D      128
#define TWO_D  256
#define SEG    50000

#define NEG_INF __int_as_float(0xFF800000)

// Scratch: device globals (no cudaMalloc allowed)
static __device__ int   g_cnt[SEG];                 // histogram
static __device__ int   g_offs[SEG + 1];            // exclusive offsets
static __device__ int   g_cur[SEG];                 // rank cursors
static __device__ int   g_perm[NE];                 // edge ids grouped by segment
static __device__ float g_cat[(size_t)SEG * TWO_D]; // [seg][0:128)=sum, [128:256)=max

// ---------------------------------------------------------------------------
// Kernel 1: zero histogram
// ---------------------------------------------------------------------------
__global__ void __launch_bounds__(256) zero_cnt_kernel() {
    int i = blockIdx.x * 256 + threadIdx.x;
    if (i < SEG) g_cnt[i] = 0;
}

// ---------------------------------------------------------------------------
// Kernel 2: histogram of index (int4 loads, fire-and-forget adds)
// ---------------------------------------------------------------------------
__global__ void __launch_bounds__(256) hist_kernel(const int* __restrict__ index) {
    int i = blockIdx.x * 256 + threadIdx.x;
    if (i < NE / 4) {
        int4 s = ((const int4*)index)[i];
        atomicAdd(&g_cnt[s.x], 1);
        atomicAdd(&g_cnt[s.y], 1);
        atomicAdd(&g_cnt[s.z], 1);
        atomicAdd(&g_cnt[s.w], 1);
    }
}

// ---------------------------------------------------------------------------
// Kernel 3: exclusive scan of 50K counters. One block, 1024 threads.
// ---------------------------------------------------------------------------
__global__ void __launch_bounds__(1024) scan_kernel() {
    __shared__ int part[1024];
    const int CH = 49;                     // 1024*49 = 50176 >= 50000
    int t  = threadIdx.x;
    int lo = t * CH;
    int hi = lo + CH; if (hi > SEG) hi = SEG;
    if (lo > SEG) lo = SEG;

    int s = 0;
    for (int i = lo; i < hi; i++) s += g_cnt[i];
    part[t] = s;
    __syncthreads();

    for (int off = 1; off < 1024; off <<= 1) {
        int v = 0;
        if (t >= off) v = part[t - off];
        __syncthreads();
        if (t >= off) part[t] += v;
        __syncthreads();
    }

    int run = (t == 0) ? 0 : part[t - 1];
    for (int i = lo; i < hi; i++) {
        g_offs[i] = run;
        g_cur[i]  = run;
        run += g_cnt[i];
    }
    if (t == 1023) g_offs[SEG] = part[1023];
}

// ---------------------------------------------------------------------------
// Kernel 4: build permutation (edges grouped by segment)
// ---------------------------------------------------------------------------
__global__ void __launch_bounds__(256) rank_kernel(const int* __restrict__ index) {
    int e = blockIdx.x * 256 + threadIdx.x;
    if (e < NE) {
        int seg = index[e];
        int pos = atomicAdd(&g_cur[seg], 1);
        g_perm[pos] = e;
    }
}

// ---------------------------------------------------------------------------
// Kernel 5: segment reduce. One warp per segment; lane owns 4 features.
// Streaming float4 loads, register accumulation, unroll x4 for MLP.
// Writes one 256-wide row of g_cat (sum | max). Empty segments -> max = 0.
// ---------------------------------------------------------------------------
__global__ void __launch_bounds__(256) reduce_kernel(const float* __restrict__ src) {
    int seg  = blockIdx.x * 8 + (threadIdx.x >> 5);
    int lane = threadIdx.x & 31;
    if (seg >= SEG) return;

    int start = __ldg(&g_offs[seg]);
    int end   = __ldg(&g_offs[seg + 1]);

    float4 sum = make_float4(0.f, 0.f, 0.f, 0.f);
    float4 mx  = make_float4(NEG_INF, NEG_INF, NEG_INF, NEG_INF);

    int i = start;
    for (; i + 3 < end; i += 4) {
        int e0 = __ldg(&g_perm[i]);
        int e1 = __ldg(&g_perm[i + 1]);
        int e2 = __ldg(&g_perm[i + 2]);
        int e3 = __ldg(&g_perm[i + 3]);
        float4 v0 = __ldcs((const float4*)(src + (size_t)e0 * D) + lane);
        float4 v1 = __ldcs((const float4*)(src + (size_t)e1 * D) + lane);
        float4 v2 = __ldcs((const float4*)(src + (size_t)e2 * D) + lane);
        float4 v3 = __ldcs((const float4*)(src + (size_t)e3 * D) + lane);
        sum.x += v0.x + v1.x; sum.y += v0.y + v1.y;
        sum.z += v0.z + v1.z; sum.w += v0.w + v1.w;
        sum.x += v2.x + v3.x; sum.y += v2.y + v3.y;
        sum.z += v2.z + v3.z; sum.w += v2.w + v3.w;
        mx.x = fmaxf(fmaxf(mx.x, v0.x), fmaxf(v1.x, fmaxf(v2.x, v3.x)));
        mx.y = fmaxf(fmaxf(mx.y, v0.y), fmaxf(v1.y, fmaxf(v2.y, v3.y)));
        mx.z = fmaxf(fmaxf(mx.z, v0.z), fmaxf(v1.z, fmaxf(v2.z, v3.z)));
        mx.w = fmaxf(fmaxf(mx.w, v0.w), fmaxf(v1.w, fmaxf(v2.w, v3.w)));
    }
    for (; i < end; i++) {
        int e0 = __ldg(&g_perm[i]);
        float4 v0 = __ldcs((const float4*)(src + (size_t)e0 * D) + lane);
        sum.x += v0.x; sum.y += v0.y; sum.z += v0.z; sum.w += v0.w;
        mx.x = fmaxf(mx.x, v0.x); mx.y = fmaxf(mx.y, v0.y);
        mx.z = fmaxf(mx.z, v0.z); mx.w = fmaxf(mx.w, v0.w);
    }

    if (start == end)                 // torch_scatter: empty max = 0
        mx = make_float4(0.f, 0.f, 0.f, 0.f);

    size_t base = (size_t)seg * TWO_D + (size_t)lane * 4;
    *(float4*)(g_cat + base)     = sum;
    *(float4*)(g_cat + base + D) = mx;
}

// ---------------------------------------------------------------------------
// Kernel 6: out[n, d] = sum_k g_cat[n, k] * W[d, k] + b[d]
// Block tile 64 rows x 128 cols, BK = 32. 256 threads: lane tx -> col pairs
// (2tx, 2tx+1) and (64+2tx, 64+2tx+1) [conflict-free LDS.64 at 2-phase floor];
// warp ty -> rows ty*8..ty*8+7. As stored row-major [m][k] (stride 36: STS.128
// phases bank-perfect; reads are warp broadcasts). FFMA2 accumulators.
// ---------------------------------------------------------------------------
#define BM  64
#define BK  32
#define ASS 36    // As row stride (words): 32 + 4 pad
#define BSS 132   // Bs row stride (words): 128 + 4 pad

__global__ void __launch_bounds__(256) gemm_kernel(const float* __restrict__ W,
                                                   const float* __restrict__ bias,
                                                   float* __restrict__ out) {
    __shared__ float As[BM * ASS];   // As[m][k]
    __shared__ float Bs[BK * BSS];   // Bs[k][d]

    int tid  = threadIdx.x;
    int tx   = tid & 31;   // col pairs (2tx, 2tx+1), (64+2tx, 64+2tx+1)
    int ty   = tid >> 5;   // rows ty*8 .. ty*8+7
    int row0 = blockIdx.x * BM;

    unsigned long long acc2[8][2];
    #pragma unroll
    for (int i = 0; i < 8; i++) { acc2[i][0] = 0ull; acc2[i][1] = 0ull; }

    for (int kc = 0; kc < TWO_D; kc += BK) {
        // --- stage A tile: 64 rows x 32 k = 512 float4, 2 per thread ---
        #pragma unroll
        for (int l = 0; l < 2; l++) {
            int idx = tid + l * 256;
            int m   = idx >> 3;
            int k4  = (idx & 7) * 4;
            int gr  = row0 + m;
            float4 v = make_float4(0.f, 0.f, 0.f, 0.f);
            if (gr < SEG)
                v = *(const float4*)(g_cat + (size_t)gr * TWO_D + kc + k4);
            *(float4*)(As + m * ASS + k4) = v;
        }
        // --- stage B tile: Bs[k][d] = W[d][kc+k]; 1024 float4, 4 per thread ---
        #pragma unroll
        for (int l = 0; l < 4; l++) {
            int idx = tid + l * 256;
            int d   = idx >> 3;
            int k4  = (idx & 7) * 4;
            float4 v = *(const float4*)(W + (size_t)d * TWO_D + kc + k4);
            Bs[(k4 + 0) * BSS + d] = v.x;
            Bs[(k4 + 1) * BSS + d] = v.y;
            Bs[(k4 + 2) * BSS + d] = v.z;
            Bs[(k4 + 3) * BSS + d] = v.w;
        }
        __syncthreads();

        #pragma unroll
        for (int kk = 0; kk < BK; kk += 4) {
            // 8 rows x 4 k-values, loaded as broadcast LDS.128
            float a[8][4];
            #pragma unroll
            for (int i = 0; i < 8; i++)
                *(float4*)a[i] = *(const float4*)(As + (ty * 8 + i) * ASS + kk);

            #pragma unroll
            for (int q = 0; q < 4; q++) {
                unsigned long long b0 = *(const unsigned long long*)(Bs + (kk + q) * BSS + 2 * tx);
                unsigned long long b1 = *(const unsigned long long*)(Bs + (kk + q) * BSS + 64 + 2 * tx);
                #pragma unroll
                for (int i = 0; i < 8; i++) {
                    unsigned long long asplat;
                    asm("mov.b64 %0, {%1, %1};" : "=l"(asplat) : "f"(a[i][q]));
                    asm("fma.rn.f32x2 %0, %1, %2, %0;" : "+l"(acc2[i][0]) : "l"(asplat), "l"(b0));
                    asm("fma.rn.f32x2 %0, %1, %2, %0;" : "+l"(acc2[i][1]) : "l"(asplat), "l"(b1));
                }
            }
        }
        __syncthreads();
    }

    float2 bb0 = *(const float2*)(bias + 2 * tx);
    float2 bb1 = *(const float2*)(bias + 64 + 2 * tx);
    #pragma unroll
    for (int i = 0; i < 8; i++) {
        int gr = row0 + ty * 8 + i;
        if (gr < SEG) {
            float x0, x1, x2, x3;
            asm("mov.b64 {%0, %1}, %2;" : "=f"(x0), "=f"(x1) : "l"(acc2[i][0]));
            asm("mov.b64 {%0, %1}, %2;" : "=f"(x2), "=f"(x3) : "l"(acc2[i][1]));
            *(float2*)(out + (size_t)gr * D + 2 * tx)      = make_float2(x0 + bb0.x, x1 + bb0.y);
            *(float2*)(out + (size_t)gr * D + 64 + 2 * tx) = make_float2(x2 + bb1.x, x3 + bb1.y);
        }
    }
}

// ---------------------------------------------------------------------------
// Launch pipeline: zero -> hist -> scan -> rank -> reduce -> gemm
// Inputs (metadata order): src[f32 NE*D], index[i32 NE], W[f32 D*2D], b[f32 D]
// ---------------------------------------------------------------------------
extern "C" void kernel_launch(void* const* d_in, const int* in_sizes, int n_in,
                              void* d_out, int out_size) {
    const float* src   = (const float*)d_in[0];
    const int*   index = (const int*)d_in[1];
    const float* W     = (const float*)d_in[2];
    const float* bias  = (const float*)d_in[3];
    float* out = (float*)d_out;

    (void)in_sizes; (void)n_in; (void)out_size;

    zero_cnt_kernel<<<(SEG + 255) / 256, 256>>>();
    hist_kernel<<<(NE / 4 + 255) / 256, 256>>>(index);
    scan_kernel<<<1, 1024>>>();
    rank_kernel<<<(NE + 255) / 256, 256>>>(index);
    reduce_kernel<<<SEG / 8, 256>>>(src);
    gemm_kernel<<<(SEG + BM - 1) / BM, 256>>>(W, bias, out);
}

// round 5
// speedup vs baseline: 1.1244x; 1.0076x over previous
#include <cuda_runtime.h>
#include <cstdint>

// Problem constants (fixed by the dataset)
#define NE     1600000
#define D      128
#define TWO_D  256
#define SEG    50000

#define NEG_INF __int_as_float(0xFF800000)

// Scratch: device globals (no cudaMalloc allowed)
static __device__ int   g_cnt[SEG];                 // histogram
static __device__ int   g_offs[SEG + 1];            // exclusive offsets
static __device__ int   g_cur[SEG];                 // rank cursors
static __device__ int   g_perm[NE];                 // edge ids grouped by segment
static __device__ float g_cat[(size_t)SEG * TWO_D]; // [seg][0:128)=sum, [128:256)=max

// ---------------------------------------------------------------------------
// Kernel 1: zero histogram
// ---------------------------------------------------------------------------
__global__ void __launch_bounds__(256) zero_cnt_kernel() {
    int i = blockIdx.x * 256 + threadIdx.x;
    if (i < SEG) g_cnt[i] = 0;
}

// ---------------------------------------------------------------------------
// Kernel 2: histogram of index (int4 loads, fire-and-forget adds)
// ---------------------------------------------------------------------------
__global__ void __launch_bounds__(256) hist_kernel(const int* __restrict__ index) {
    int i = blockIdx.x * 256 + threadIdx.x;
    if (i < NE / 4) {
        int4 s = ((const int4*)index)[i];
        atomicAdd(&g_cnt[s.x], 1);
        atomicAdd(&g_cnt[s.y], 1);
        atomicAdd(&g_cnt[s.z], 1);
        atomicAdd(&g_cnt[s.w], 1);
    }
}

// ---------------------------------------------------------------------------
// Kernel 3: exclusive scan of 50K counters. One block, 1024 threads.
// ---------------------------------------------------------------------------
__global__ void __launch_bounds__(1024) scan_kernel() {
    __shared__ int part[1024];
    const int CH = 49;                     // 1024*49 = 50176 >= 50000
    int t  = threadIdx.x;
    int lo = t * CH;
    int hi = lo + CH; if (hi > SEG) hi = SEG;
    if (lo > SEG) lo = SEG;

    int s = 0;
    for (int i = lo; i < hi; i++) s += g_cnt[i];
    part[t] = s;
    __syncthreads();

    for (int off = 1; off < 1024; off <<= 1) {
        int v = 0;
        if (t >= off) v = part[t - off];
        __syncthreads();
        if (t >= off) part[t] += v;
        __syncthreads();
    }

    int run = (t == 0) ? 0 : part[t - 1];
    for (int i = lo; i < hi; i++) {
        g_offs[i] = run;
        g_cur[i]  = run;
        run += g_cnt[i];
    }
    if (t == 1023) g_offs[SEG] = part[1023];
}

// ---------------------------------------------------------------------------
// Kernel 4: build permutation (edges grouped by segment)
// ---------------------------------------------------------------------------
__global__ void __launch_bounds__(256) rank_kernel(const int* __restrict__ index) {
    int e = blockIdx.x * 256 + threadIdx.x;
    if (e < NE) {
        int seg = index[e];
        int pos = atomicAdd(&g_cur[seg], 1);
        g_perm[pos] = e;
    }
}

// ---------------------------------------------------------------------------
// Kernel 5: segment reduce. One warp per segment; lane owns 4 features.
// Streaming float4 loads, register accumulation, unroll x4 for MLP.
// Writes one 256-wide row of g_cat (sum | max). Empty segments -> max = 0.
// ---------------------------------------------------------------------------
__global__ void __launch_bounds__(256) reduce_kernel(const float* __restrict__ src) {
    int seg  = blockIdx.x * 8 + (threadIdx.x >> 5);
    int lane = threadIdx.x & 31;
    if (seg >= SEG) return;

    int start = __ldg(&g_offs[seg]);
    int end   = __ldg(&g_offs[seg + 1]);

    float4 sum = make_float4(0.f, 0.f, 0.f, 0.f);
    float4 mx  = make_float4(NEG_INF, NEG_INF, NEG_INF, NEG_INF);

    int i = start;
    for (; i + 3 < end; i += 4) {
        int e0 = __ldg(&g_perm[i]);
        int e1 = __ldg(&g_perm[i + 1]);
        int e2 = __ldg(&g_perm[i + 2]);
        int e3 = __ldg(&g_perm[i + 3]);
        float4 v0 = __ldcs((const float4*)(src + (size_t)e0 * D) + lane);
        float4 v1 = __ldcs((const float4*)(src + (size_t)e1 * D) + lane);
        float4 v2 = __ldcs((const float4*)(src + (size_t)e2 * D) + lane);
        float4 v3 = __ldcs((const float4*)(src + (size_t)e3 * D) + lane);
        sum.x += v0.x + v1.x; sum.y += v0.y + v1.y;
        sum.z += v0.z + v1.z; sum.w += v0.w + v1.w;
        sum.x += v2.x + v3.x; sum.y += v2.y + v3.y;
        sum.z += v2.z + v3.z; sum.w += v2.w + v3.w;
        mx.x = fmaxf(fmaxf(mx.x, v0.x), fmaxf(v1.x, fmaxf(v2.x, v3.x)));
        mx.y = fmaxf(fmaxf(mx.y, v0.y), fmaxf(v1.y, fmaxf(v2.y, v3.y)));
        mx.z = fmaxf(fmaxf(mx.z, v0.z), fmaxf(v1.z, fmaxf(v2.z, v3.z)));
        mx.w = fmaxf(fmaxf(mx.w, v0.w), fmaxf(v1.w, fmaxf(v2.w, v3.w)));
    }
    for (; i < end; i++) {
        int e0 = __ldg(&g_perm[i]);
        float4 v0 = __ldcs((const float4*)(src + (size_t)e0 * D) + lane);
        sum.x += v0.x; sum.y += v0.y; sum.z += v0.z; sum.w += v0.w;
        mx.x = fmaxf(mx.x, v0.x); mx.y = fmaxf(mx.y, v0.y);
        mx.z = fmaxf(mx.z, v0.z); mx.w = fmaxf(mx.w, v0.w);
    }

    if (start == end)                 // torch_scatter: empty max = 0
        mx = make_float4(0.f, 0.f, 0.f, 0.f);

    size_t base = (size_t)seg * TWO_D + (size_t)lane * 4;
    *(float4*)(g_cat + base)     = sum;
    *(float4*)(g_cat + base + D) = mx;
}

// ---------------------------------------------------------------------------
// Kernel 6: out[n, d] = sum_k g_cat[n, k] * W[d, k] + b[d]
// Row-pair-packed FFMA2 GEMM, zero MOVs in the hot loop:
//   - As[k][m] k-major: ulonglong2 LDS.128 yields two naturally packed
//     row pairs (warp-broadcast, conflict-free).
//   - Bs[k][2d] stores W DUPLICATED, so LDS.64 directly yields the b-splat.
// Tile 128 rows x 128 cols, BK=16, 256 threads. Warp w owns rows
// [16w,16w+16) (8 pairs); lane owns cols {lane, lane+32, lane+64, lane+96}.
// Per k per thread: 4 LDS.128 + 4 LDS.64 + 32 FFMA2 -> FFMA2-issue-bound.
// ---------------------------------------------------------------------------
#define BM   128
#define BK   16
#define AMS  132   // As row stride (words)
#define BS2S 258   // Bs row stride (words, duplicated layout)

__global__ void __launch_bounds__(256) gemm_kernel(const float* __restrict__ W,
                                                   const float* __restrict__ bias,
                                                   float* __restrict__ out) {
    __shared__ float As[BK * AMS];     // As[k][m]
    __shared__ float Bs[BK * BS2S];    // Bs[k][2d] = Bs[k][2d+1] = W[d][k]

    int tid  = threadIdx.x;
    int w    = tid >> 5;    // rows 16w .. 16w+15
    int lane = tid & 31;    // cols lane + 32c
    int row0 = blockIdx.x * BM;

    unsigned long long acc[8][4];   // [row pair p][col c]
    #pragma unroll
    for (int p = 0; p < 8; p++)
        #pragma unroll
        for (int c = 0; c < 4; c++) acc[p][c] = 0ull;

    for (int kc = 0; kc < TWO_D; kc += BK) {
        // --- stage A: 128 m x 16 k = 512 float4, 2 per thread ---
        #pragma unroll
        for (int l = 0; l < 2; l++) {
            int idx = tid + l * 256;
            int m   = idx >> 2;          // 0..127
            int k4  = (idx & 3) * 4;     // 0,4,8,12
            int gr  = row0 + m;
            float4 v = make_float4(0.f, 0.f, 0.f, 0.f);
            if (gr < SEG)
                v = *(const float4*)(g_cat + (size_t)gr * TWO_D + kc + k4);
            As[(k4 + 0) * AMS + m] = v.x;
            As[(k4 + 1) * AMS + m] = v.y;
            As[(k4 + 2) * AMS + m] = v.z;
            As[(k4 + 3) * AMS + m] = v.w;
        }
        // --- stage B duplicated: 128 d x 16 k = 512 float4, 2 per thread ---
        #pragma unroll
        for (int l = 0; l < 2; l++) {
            int idx = tid + l * 256;
            int d   = idx >> 2;          // 0..127
            int k4  = (idx & 3) * 4;
            float4 v = *(const float4*)(W + (size_t)d * TWO_D + kc + k4);
            float vv[4] = {v.x, v.y, v.z, v.w};
            #pragma unroll
            for (int q = 0; q < 4; q++) {
                unsigned long long dup;
                asm("mov.b64 %0, {%1, %1};" : "=l"(dup) : "f"(vv[q]));
                *(unsigned long long*)(Bs + (k4 + q) * BS2S + 2 * d) = dup;
            }
        }
        __syncthreads();

        #pragma unroll
        for (int k = 0; k < BK; k++) {
            // A: 4x LDS.128 broadcast -> 8 packed row pairs
            unsigned long long ap[8];
            #pragma unroll
            for (int g = 0; g < 4; g++) {
                ulonglong2 a2 = *(const ulonglong2*)(As + k * AMS + 16 * w + 4 * g);
                ap[2 * g]     = a2.x;
                ap[2 * g + 1] = a2.y;
            }
            // B: 4x LDS.64 -> pre-duplicated splats
            unsigned long long bs[4];
            #pragma unroll
            for (int c = 0; c < 4; c++)
                bs[c] = *(const unsigned long long*)(Bs + k * BS2S + 2 * (lane + 32 * c));

            #pragma unroll
            for (int p = 0; p < 8; p++)
                #pragma unroll
                for (int c = 0; c < 4; c++)
                    asm("fma.rn.f32x2 %0, %1, %2, %0;"
                        : "+l"(acc[p][c]) : "l"(ap[p]), "l"(bs[c]));
        }
        __syncthreads();
    }

    float bb[4];
    #pragma unroll
    for (int c = 0; c < 4; c++) bb[c] = __ldg(bias + lane + 32 * c);

    #pragma unroll
    for (int p = 0; p < 8; p++) {
        int gr0 = row0 + 16 * w + 2 * p;
        #pragma unroll
        for (int c = 0; c < 4; c++) {
            float r0, r1;
            asm("mov.b64 {%0, %1}, %2;" : "=f"(r0), "=f"(r1) : "l"(acc[p][c]));
            int col = lane + 32 * c;
            if (gr0 < SEG)     out[(size_t)gr0 * D + col]       = r0 + bb[c];
            if (gr0 + 1 < SEG) out[(size_t)(gr0 + 1) * D + col] = r1 + bb[c];
        }
    }
}

// ---------------------------------------------------------------------------
// Launch pipeline: zero -> hist -> scan -> rank -> reduce -> gemm
// Inputs (metadata order): src[f32 NE*D], index[i32 NE], W[f32 D*2D], b[f32 D]
// ---------------------------------------------------------------------------
extern "C" void kernel_launch(void* const* d_in, const int* in_sizes, int n_in,
                              void* d_out, int out_size) {
    const float* src   = (const float*)d_in[0];
    const int*   index = (const int*)d_in[1];
    const float* W     = (const float*)d_in[2];
    const float* bias  = (const float*)d_in[3];
    float* out = (float*)d_out;

    (void)in_sizes; (void)n_in; (void)out_size;

    zero_cnt_kernel<<<(SEG + 255) / 256, 256>>>();
    hist_kernel<<<(NE / 4 + 255) / 256, 256>>>(index);
    scan_kernel<<<1, 1024>>>();
    rank_kernel<<<(NE + 255) / 256, 256>>>(index);
    reduce_kernel<<<SEG / 8, 256>>>(src);
    gemm_kernel<<<(SEG + BM - 1) / BM, 256>>>(W, bias, out);
}

// round 6
// speedup vs baseline: 1.1742x; 1.0443x over previous
#include <cuda_runtime.h>
#include <cstdint>

// Problem constants (fixed by the dataset)
#define NE     1600000
#define D      128
#define TWO_D  256
#define SEG    50000

#define NEG_INF __int_as_float(0xFF800000)

// Scratch: device globals (no cudaMalloc allowed).
// g_cnt is zero at module load; scan_kernel re-zeroes it after use so every
// replay of the captured graph sees zeroed counters.
static __device__ int   g_cnt[SEG];                 // histogram (self-cleaning)
static __device__ int   g_offs[SEG + 1];            // exclusive offsets
static __device__ int   g_rank[NE];                 // per-edge rank within segment
static __device__ int   g_perm[NE];                 // edge ids grouped by segment
static __device__ float g_cat[(size_t)SEG * TWO_D]; // [seg][0:128)=sum, [128:256)=max

// ---------------------------------------------------------------------------
// Kernel 1: fused histogram + rank. One atomic pass: r[e] = old count.
// ---------------------------------------------------------------------------
__global__ void __launch_bounds__(256) hist_rank_kernel(const int* __restrict__ index) {
    int i = blockIdx.x * 256 + threadIdx.x;
    if (i < NE / 4) {
        int4 s = ((const int4*)index)[i];
        int4 r;
        r.x = atomicAdd(&g_cnt[s.x], 1);
        r.y = atomicAdd(&g_cnt[s.y], 1);
        r.z = atomicAdd(&g_cnt[s.z], 1);
        r.w = atomicAdd(&g_cnt[s.w], 1);
        ((int4*)g_rank)[i] = r;
    }
}

// ---------------------------------------------------------------------------
// Kernel 2: exclusive scan of 50K counters; zeroes g_cnt afterwards so the
// next graph replay starts clean. One block, 1024 threads.
// ---------------------------------------------------------------------------
__global__ void __launch_bounds__(1024) scan_kernel() {
    __shared__ int part[1024];
    const int CH = 49;                     // 1024*49 = 50176 >= 50000
    int t  = threadIdx.x;
    int lo = t * CH;
    int hi = lo + CH; if (hi > SEG) hi = SEG;
    if (lo > SEG) lo = SEG;

    int cnt[CH];
    int s = 0;
    for (int i = lo; i < hi; i++) { cnt[i - lo] = g_cnt[i]; s += cnt[i - lo]; }
    part[t] = s;
    __syncthreads();

    for (int off = 1; off < 1024; off <<= 1) {
        int v = 0;
        if (t >= off) v = part[t - off];
        __syncthreads();
        if (t >= off) part[t] += v;
        __syncthreads();
    }

    int run = (t == 0) ? 0 : part[t - 1];
    for (int i = lo; i < hi; i++) {
        g_offs[i] = run;
        g_cnt[i]  = 0;                     // self-clean for next replay
        run += cnt[i - lo];
    }
    if (t == 1023) g_offs[SEG] = part[1023];
}

// ---------------------------------------------------------------------------
// Kernel 3: atomic-free permutation scatter: perm[offs[seg] + r[e]] = e.
// Pure loads + fire-and-forget scattered stores.
// ---------------------------------------------------------------------------
__global__ void __launch_bounds__(256) perm_kernel(const int* __restrict__ index) {
    int i = blockIdx.x * 256 + threadIdx.x;
    if (i < NE / 4) {
        int4 s = ((const int4*)index)[i];
        int4 r = ((const int4*)g_rank)[i];
        int e = i * 4;
        g_perm[__ldg(&g_offs[s.x]) + r.x] = e;
        g_perm[__ldg(&g_offs[s.y]) + r.y] = e + 1;
        g_perm[__ldg(&g_offs[s.z]) + r.z] = e + 2;
        g_perm[__ldg(&g_offs[s.w]) + r.w] = e + 3;
    }
}

// ---------------------------------------------------------------------------
// Kernel 4: segment reduce. One warp per segment; lane owns 4 features.
// Unroll x8: 8 independent 512B gathers in flight per warp.
// Writes one 256-wide row of g_cat (sum | max). Empty segments -> max = 0.
// ---------------------------------------------------------------------------
__global__ void __launch_bounds__(256) reduce_kernel(const float* __restrict__ src) {
    int seg  = blockIdx.x * 8 + (threadIdx.x >> 5);
    int lane = threadIdx.x & 31;
    if (seg >= SEG) return;

    int start = __ldg(&g_offs[seg]);
    int end   = __ldg(&g_offs[seg + 1]);

    float4 sum = make_float4(0.f, 0.f, 0.f, 0.f);
    float4 mx  = make_float4(NEG_INF, NEG_INF, NEG_INF, NEG_INF);

    int i = start;
    for (; i + 7 < end; i += 8) {
        int e[8];
        #pragma unroll
        for (int j = 0; j < 8; j++) e[j] = __ldg(&g_perm[i + j]);
        float4 v[8];
        #pragma unroll
        for (int j = 0; j < 8; j++)
            v[j] = __ldcs((const float4*)(src + (size_t)e[j] * D) + lane);
        #pragma unroll
        for (int j = 0; j < 8; j++) {
            sum.x += v[j].x; sum.y += v[j].y; sum.z += v[j].z; sum.w += v[j].w;
            mx.x = fmaxf(mx.x, v[j].x); mx.y = fmaxf(mx.y, v[j].y);
            mx.z = fmaxf(mx.z, v[j].z); mx.w = fmaxf(mx.w, v[j].w);
        }
    }
    for (; i < end; i++) {
        int e0 = __ldg(&g_perm[i]);
        float4 v0 = __ldcs((const float4*)(src + (size_t)e0 * D) + lane);
        sum.x += v0.x; sum.y += v0.y; sum.z += v0.z; sum.w += v0.w;
        mx.x = fmaxf(mx.x, v0.x); mx.y = fmaxf(mx.y, v0.y);
        mx.z = fmaxf(mx.z, v0.z); mx.w = fmaxf(mx.w, v0.w);
    }

    if (start == end)                 // torch_scatter: empty max = 0
        mx = make_float4(0.f, 0.f, 0.f, 0.f);

    size_t base = (size_t)seg * TWO_D + (size_t)lane * 4;
    *(float4*)(g_cat + base)     = sum;
    *(float4*)(g_cat + base + D) = mx;
}

// ---------------------------------------------------------------------------
// Kernel 5: out[n, d] = sum_k g_cat[n, k] * W[d, k] + b[d]
// Row-pair-packed FFMA2 GEMM, zero MOVs in the hot loop.
// ---------------------------------------------------------------------------
#define BM   128
#define BK   16
#define AMS  132   // As row stride (words)
#define BS2S 258   // Bs row stride (words, duplicated layout)

__global__ void __launch_bounds__(256) gemm_kernel(const float* __restrict__ W,
                                                   const float* __restrict__ bias,
                                                   float* __restrict__ out) {
    __shared__ float As[BK * AMS];     // As[k][m]
    __shared__ float Bs[BK * BS2S];    // Bs[k][2d] = Bs[k][2d+1] = W[d][k]

    int tid  = threadIdx.x;
    int w    = tid >> 5;    // rows 16w .. 16w+15
    int lane = tid & 31;    // cols lane + 32c
    int row0 = blockIdx.x * BM;

    unsigned long long acc[8][4];   // [row pair p][col c]
    #pragma unroll
    for (int p = 0; p < 8; p++)
        #pragma unroll
        for (int c = 0; c < 4; c++) acc[p][c] = 0ull;

    for (int kc = 0; kc < TWO_D; kc += BK) {
        #pragma unroll
        for (int l = 0; l < 2; l++) {
            int idx = tid + l * 256;
            int m   = idx >> 2;          // 0..127
            int k4  = (idx & 3) * 4;     // 0,4,8,12
            int gr  = row0 + m;
            float4 v = make_float4(0.f, 0.f, 0.f, 0.f);
            if (gr < SEG)
                v = *(const float4*)(g_cat + (size_t)gr * TWO_D + kc + k4);
            As[(k4 + 0) * AMS + m] = v.x;
            As[(k4 + 1) * AMS + m] = v.y;
            As[(k4 + 2) * AMS + m] = v.z;
            As[(k4 + 3) * AMS + m] = v.w;
        }
        #pragma unroll
        for (int l = 0; l < 2; l++) {
            int idx = tid + l * 256;
            int d   = idx >> 2;          // 0..127
            int k4  = (idx & 3) * 4;
            float4 v = *(const float4*)(W + (size_t)d * TWO_D + kc + k4);
            float vv[4] = {v.x, v.y, v.z, v.w};
            #pragma unroll
            for (int q = 0; q < 4; q++) {
                unsigned long long dup;
                asm("mov.b64 %0, {%1, %1};" : "=l"(dup) : "f"(vv[q]));
                *(unsigned long long*)(Bs + (k4 + q) * BS2S + 2 * d) = dup;
            }
        }
        __syncthreads();

        #pragma unroll
        for (int k = 0; k < BK; k++) {
            unsigned long long ap[8];
            #pragma unroll
            for (int g = 0; g < 4; g++) {
                ulonglong2 a2 = *(const ulonglong2*)(As + k * AMS + 16 * w + 4 * g);
                ap[2 * g]     = a2.x;
                ap[2 * g + 1] = a2.y;
            }
            unsigned long long bs[4];
            #pragma unroll
            for (int c = 0; c < 4; c++)
                bs[c] = *(const unsigned long long*)(Bs + k * BS2S + 2 * (lane + 32 * c));

            #pragma unroll
            for (int p = 0; p < 8; p++)
                #pragma unroll
                for (int c = 0; c < 4; c++)
                    asm("fma.rn.f32x2 %0, %1, %2, %0;"
                        : "+l"(acc[p][c]) : "l"(ap[p]), "l"(bs[c]));
        }
        __syncthreads();
    }

    float bb[4];
    #pragma unroll
    for (int c = 0; c < 4; c++) bb[c] = __ldg(bias + lane + 32 * c);

    #pragma unroll
    for (int p = 0; p < 8; p++) {
        int gr0 = row0 + 16 * w + 2 * p;
        #pragma unroll
        for (int c = 0; c < 4; c++) {
            float r0, r1;
            asm("mov.b64 {%0, %1}, %2;" : "=f"(r0), "=f"(r1) : "l"(acc[p][c]));
            int col = lane + 32 * c;
            if (gr0 < SEG)     out[(size_t)gr0 * D + col]       = r0 + bb[c];
            if (gr0 + 1 < SEG) out[(size_t)(gr0 + 1) * D + col] = r1 + bb[c];
        }
    }
}

// ---------------------------------------------------------------------------
// Launch pipeline: hist_rank -> scan(+clean) -> perm -> reduce -> gemm
// Inputs (metadata order): src[f32 NE*D], index[i32 NE], W[f32 D*2D], b[f32 D]
// ---------------------------------------------------------------------------
extern "C" void kernel_launch(void* const* d_in, const int* in_sizes, int n_in,
                              void* d_out, int out_size) {
    const float* src   = (const float*)d_in[0];
    const int*   index = (const int*)d_in[1];
    const float* W     = (const float*)d_in[2];
    const float* bias  = (const float*)d_in[3];
    float* out = (float*)d_out;

    (void)in_sizes; (void)n_in; (void)out_size;

    hist_rank_kernel<<<(NE / 4 + 255) / 256, 256>>>(index);
    scan_kernel<<<1, 1024>>>();
    perm_kernel<<<(NE / 4 + 255) / 256, 256>>>(index);
    reduce_kernel<<<SEG / 8, 256>>>(src);
    gemm_kernel<<<(SEG + BM - 1) / BM, 256>>>(W, bias, out);
}